// round 2
// baseline (speedup 1.0000x reference)
#include <cuda_runtime.h>

// QuantumSelfAttention: softmax(z,-1).mean(-1) == 1/4 exactly for every sample
// (rows of a softmax sum to 1; mean over that axis is 1/numel). The entire
// quantum circuit is dead code w.r.t. the output. Output = 0.25 everywhere.
//
// out_size = 2048*256 = 524288 floats (2 MiB). Launch-overhead bound:
// 2 MiB of L2-resident stores is ~0.2us of real work; minimize CTA count and
// per-thread instruction count instead.

// Each thread writes 4 consecutive float4 (64 B). Exact cover, no bounds check.
__global__ void __launch_bounds__(256, 1)
qsa_fill64_kernel(float4* __restrict__ out4) {
    const float4 v = make_float4(0.25f, 0.25f, 0.25f, 0.25f);
    int base = (blockIdx.x * 256 + threadIdx.x) * 4;
#pragma unroll
    for (int j = 0; j < 4; ++j)
        out4[base + j] = v;
}

// Fallback scalar tail (unreachable for this problem's out_size, kept for safety).
__global__ void qsa_fill_tail_kernel(float* __restrict__ out, int start, int n) {
    int i = start + blockIdx.x * blockDim.x + threadIdx.x;
    if (i < n) out[i] = 0.25f;
}

extern "C" void kernel_launch(void* const* d_in, const int* in_sizes, int n_in,
                              void* d_out, int out_size) {
    (void)d_in; (void)in_sizes; (void)n_in;

    float* out = (float*)d_out;
    // Elements covered by the vector kernel: multiples of 16 floats per thread-quad.
    int n_vec = out_size & ~15;            // floats covered by 64B-per-thread kernel
    int n_threads = n_vec >> 4;            // 4 float4 per thread
    if (n_threads > 0) {
        int blocks = n_threads / 256;      // out_size=524288 -> 32768 threads -> 128 blocks
        if (blocks * 256 != n_threads) {
            // General fallback: revert to grid-stride single-float4 (not hit here)
            blocks = (n_threads + 255) / 256;
        }
        qsa_fill64_kernel<<<blocks, 256>>>((float4*)out);
    }
    if (n_vec < out_size) {
        int rem = out_size - n_vec;
        qsa_fill_tail_kernel<<<(rem + 255) / 256, 256>>>(out, n_vec, out_size);
    }
}

// round 3
// speedup vs baseline: 1.0062x; 1.0062x over previous
#include <cuda_runtime.h>

// QuantumSelfAttention: softmax(z,-1).mean(-1) == 1/4 exactly for every sample
// (softmax rows sum to 1; mean over that axis = 1/4). Entire circuit is dead
// code w.r.t. the output. Output = 0.25 everywhere.
//
// out_size = 524288 floats (2 MiB, L2-resident). Kernel is launch-floor bound
// (~4us vs ~0.2us of store work). Fastest shape measured: maximum grid width,
// one 128-bit store per thread, no loop, no bounds check (exact cover).

__global__ void __launch_bounds__(256, 1)
qsa_fill_exact_kernel(float4* __restrict__ out4) {
    out4[blockIdx.x * 256 + threadIdx.x] =
        make_float4(0.25f, 0.25f, 0.25f, 0.25f);
}

// General fallbacks (not launched for this problem's out_size; kept for safety).
__global__ void qsa_fill_stride_kernel(float4* __restrict__ out4, int n4) {
    const float4 v = make_float4(0.25f, 0.25f, 0.25f, 0.25f);
    int idx = blockIdx.x * blockDim.x + threadIdx.x;
    int stride = gridDim.x * blockDim.x;
    for (int i = idx; i < n4; i += stride) out4[i] = v;
}
__global__ void qsa_fill_tail_kernel(float* __restrict__ out, int start, int n) {
    int i = start + blockIdx.x * blockDim.x + threadIdx.x;
    if (i < n) out[i] = 0.25f;
}

extern "C" void kernel_launch(void* const* d_in, const int* in_sizes, int n_in,
                              void* d_out, int out_size) {
    (void)d_in; (void)in_sizes; (void)n_in;

    float* out = (float*)d_out;
    int n4 = out_size >> 2;

    if ((out_size & 3) == 0 && (n4 & 255) == 0) {
        // Exact cover: one float4 per thread, 256 threads/block.
        // out_size=524288 -> n4=131072 -> 512 blocks.
        qsa_fill_exact_kernel<<<n4 / 256, 256>>>((float4*)out);
    } else {
        if (n4 > 0) {
            int blocks = (n4 + 255) / 256;
            if (blocks > 16384) blocks = 16384;
            qsa_fill_stride_kernel<<<blocks, 256>>>((float4*)out, n4);
        }
        int tail_start = n4 << 2;
        if (tail_start < out_size) {
            int rem = out_size - tail_start;
            qsa_fill_tail_kernel<<<(rem + 255) / 256, 256>>>(out, tail_start, out_size);
        }
    }
}

// round 4
// speedup vs baseline: 1.0189x; 1.0126x over previous
#include <cuda_runtime.h>

// QuantumSelfAttention: softmax(z,-1).mean(-1) == 1/4 exactly for every sample
// (softmax rows sum to 1; mean over that axis = 1/4). Entire circuit is dead
// code w.r.t. the output. Output = 0.25 everywhere.
//
// out_size = 524288 floats (2 MiB, L2-resident). Launch-floor bound:
// ~0.2us of store work inside a ~3.8us kernel. This round: same total width
// (131072 threads, one STG.128 each) but 1024-thread blocks -> 128 CTAs,
// cutting CTA dispatch ramp while keeping per-thread depth at 1 store.

__global__ void __launch_bounds__(1024, 1)
qsa_fill_exact_kernel(float4* __restrict__ out4) {
    out4[blockIdx.x * 1024 + threadIdx.x] =
        make_float4(0.25f, 0.25f, 0.25f, 0.25f);
}

// General fallbacks (not launched for this problem's out_size; kept for safety).
__global__ void qsa_fill_stride_kernel(float4* __restrict__ out4, int n4) {
    const float4 v = make_float4(0.25f, 0.25f, 0.25f, 0.25f);
    int idx = blockIdx.x * blockDim.x + threadIdx.x;
    int stride = gridDim.x * blockDim.x;
    for (int i = idx; i < n4; i += stride) out4[i] = v;
}
__global__ void qsa_fill_tail_kernel(float* __restrict__ out, int start, int n) {
    int i = start + blockIdx.x * blockDim.x + threadIdx.x;
    if (i < n) out[i] = 0.25f;
}

extern "C" void kernel_launch(void* const* d_in, const int* in_sizes, int n_in,
                              void* d_out, int out_size) {
    (void)d_in; (void)in_sizes; (void)n_in;

    float* out = (float*)d_out;
    int n4 = out_size >> 2;

    if ((out_size & 3) == 0 && (n4 & 1023) == 0) {
        // Exact cover: one float4 per thread, 1024 threads/block.
        // out_size=524288 -> n4=131072 -> 128 blocks.
        qsa_fill_exact_kernel<<<n4 / 1024, 1024>>>((float4*)out);
    } else {
        if (n4 > 0) {
            int blocks = (n4 + 255) / 256;
            if (blocks > 16384) blocks = 16384;
            qsa_fill_stride_kernel<<<blocks, 256>>>((float4*)out, n4);
        }
        int tail_start = n4 << 2;
        if (tail_start < out_size) {
            int rem = out_size - tail_start;
            qsa_fill_tail_kernel<<<(rem + 255) / 256, 256>>>(out, tail_start, out_size);
        }
    }
}